// round 2
// baseline (speedup 1.0000x reference)
#include <cuda_runtime.h>

// NCC2D: -mean( cross^2 / (I_var*J_var + 1e-5) ) with 9x9 zero-padded box sums.
// cross = IJ - I*J/81 ; I_var = I2 - I^2/81 ; J_var = J2 - J^2/81.
//
// Fused single pass:
//   grid = (col-halves=2, strips=8, images=32), 64 threads/block, 4 cols/thread.
//   Horizontal 9-tap sums via register sliding window over 12 loaded values.
//   Vertical 9-row running sums in registers; 9-deep ring of horizontal sums
//   in (thread-private) shared memory for the subtract term. No barriers in
//   the main loop. Block partial -> double atomicAdd -> finalize kernel.

#define BW   512
#define BH   512
#define NB   32
#define ROWS 64          // output rows per block (strip)
#define TPB  64          // threads per block; each owns 4 columns (256 cols/block)
#define NVEC 128         // float4 vectors per image row

__device__ double g_ncc_acc;

__global__ void ncc_init_k() { g_ncc_acc = 0.0; }

__global__ void ncc_fin_k(float* __restrict__ out) {
    out[0] = (float)(-g_ncc_acc * (1.0 / (double)((long long)NB * BH * BW)));
}

__global__ __launch_bounds__(TPB) void ncc_main_k(const float* __restrict__ gI,
                                                  const float* __restrict__ gJ) {
    __shared__ float4 ring[9 * 5 * TPB];   // [slot][product][thread] = 46080 B
    __shared__ float  wsum[TPB / 32];

    const int t  = threadIdx.x;
    const int vb = blockIdx.x * TPB + t;           // this thread's float4 index in the row
    const int r0 = blockIdx.y * ROWS;              // first output row of this strip
    const size_t img = (size_t)blockIdx.z * ((size_t)BH * BW);

    const bool leftEdge  = (vb == 0);
    const bool rightEdge = (vb == NVEC - 1);

    // Zero the (thread-private) ring slots: iterations <9 then subtract 0.
#pragma unroll
    for (int s = 0; s < 9; ++s)
#pragma unroll
        for (int p = 0; p < 5; ++p)
            ring[(s * 5 + p) * TPB + t] = make_float4(0.f, 0.f, 0.f, 0.f);

    float S[5][4];                                 // vertical running sums per product/col
#pragma unroll
    for (int p = 0; p < 5; ++p)
#pragma unroll
        for (int c = 0; c < 4; ++c) S[p][c] = 0.f;

    float acc = 0.f;
    const float inv81 = 1.0f / 81.0f;

    // Ingest rows r0-4 .. r0+ROWS+3 (72 rows = 8 chunks of 9 -> static ring slot).
    for (int base = 0; base < ROWS + 8; base += 9) {
#pragma unroll
        for (int s = 0; s < 9; ++s) {
            const int r = r0 - 4 + base + s;
            float h[5][4];
            if (r >= 0 && r < BH) {
                const float4* pI = (const float4*)(gI + img + (size_t)r * BW);
                const float4* pJ = (const float4*)(gJ + img + (size_t)r * BW);
                const float4 z = make_float4(0.f, 0.f, 0.f, 0.f);
                float4 a0 = leftEdge  ? z : __ldg(pI + (vb - 1));
                float4 a1 = __ldg(pI + vb);
                float4 a2 = rightEdge ? z : __ldg(pI + (vb + 1));
                float4 b0 = leftEdge  ? z : __ldg(pJ + (vb - 1));
                float4 b1 = __ldg(pJ + vb);
                float4 b2 = rightEdge ? z : __ldg(pJ + (vb + 1));

                float av[12] = {a0.x, a0.y, a0.z, a0.w, a1.x, a1.y, a1.z, a1.w,
                                a2.x, a2.y, a2.z, a2.w};
                float bv[12] = {b0.x, b0.y, b0.z, b0.w, b1.x, b1.y, b1.z, b1.w,
                                b2.x, b2.y, b2.z, b2.w};
                float qa[12], qb[12], qc[12];
#pragma unroll
                for (int i = 0; i < 12; ++i) {
                    qa[i] = av[i] * av[i];
                    qb[i] = bv[i] * bv[i];
                    qc[i] = av[i] * bv[i];
                }
                // First window (cols c..c+8 with c=0), then slide.
                float sI = 0.f, sJ = 0.f, sI2 = 0.f, sJ2 = 0.f, sIJ = 0.f;
#pragma unroll
                for (int k = 0; k < 9; ++k) {
                    sI += av[k]; sJ += bv[k]; sI2 += qa[k]; sJ2 += qb[k]; sIJ += qc[k];
                }
                h[0][0] = sI; h[1][0] = sJ; h[2][0] = sI2; h[3][0] = sJ2; h[4][0] = sIJ;
#pragma unroll
                for (int c = 1; c < 4; ++c) {
                    h[0][c] = h[0][c - 1] - av[c - 1] + av[c + 8];
                    h[1][c] = h[1][c - 1] - bv[c - 1] + bv[c + 8];
                    h[2][c] = h[2][c - 1] - qa[c - 1] + qa[c + 8];
                    h[3][c] = h[3][c - 1] - qb[c - 1] + qb[c + 8];
                    h[4][c] = h[4][c - 1] - qc[c - 1] + qc[c + 8];
                }
            } else {
#pragma unroll
                for (int p = 0; p < 5; ++p)
#pragma unroll
                    for (int c = 0; c < 4; ++c) h[p][c] = 0.f;
            }

            // Vertical running sums: add new row's h, subtract the h from 9 rows ago.
#pragma unroll
            for (int p = 0; p < 5; ++p) {
                float4* slot = &ring[(s * 5 + p) * TPB + t];
                float4 old = *slot;
                S[p][0] += h[p][0] - old.x;
                S[p][1] += h[p][1] - old.y;
                S[p][2] += h[p][2] - old.z;
                S[p][3] += h[p][3] - old.w;
                *slot = make_float4(h[p][0], h[p][1], h[p][2], h[p][3]);
            }

            // Output row ro = r-4 is complete once 9 rows ingested (r >= r0+4).
            if (r >= r0 + 4) {
#pragma unroll
                for (int c = 0; c < 4; ++c) {
                    float sI = S[0][c], sJ = S[1][c];
                    float cross = fmaf(sI * sJ, -inv81, S[4][c]);
                    float Iv    = fmaf(sI * sI, -inv81, S[2][c]);
                    float Jv    = fmaf(sJ * sJ, -inv81, S[3][c]);
                    float den   = fmaf(Iv, Jv, 1e-5f);
                    acc += __fdividef(cross * cross, den);
                }
            }
        }
    }

    // Block reduction -> double atomic.
#pragma unroll
    for (int o = 16; o; o >>= 1) acc += __shfl_xor_sync(0xffffffffu, acc, o);
    if ((t & 31) == 0) wsum[t >> 5] = acc;
    __syncthreads();
    if (t == 0) {
        float bs = 0.f;
#pragma unroll
        for (int w = 0; w < TPB / 32; ++w) bs += wsum[w];
        atomicAdd(&g_ncc_acc, (double)bs);
    }
}

extern "C" void kernel_launch(void* const* d_in, const int* in_sizes, int n_in,
                              void* d_out, int out_size) {
    const float* I = (const float*)d_in[0];
    const float* J = (const float*)d_in[1];
    float* out = (float*)d_out;

    ncc_init_k<<<1, 1>>>();
    dim3 grid(NVEC / TPB, BH / ROWS, NB);   // (2, 8, 32) = 512 blocks
    ncc_main_k<<<grid, TPB>>>(I, J);
    ncc_fin_k<<<1, 1>>>(out);
}